// round 14
// baseline (speedup 1.0000x reference)
#include <cuda_runtime.h>
#include <cuda_bf16.h>
#include <cstdint>

#define BATCH 32
#define MN    1024
#define DF    128
#define ED    64
#define NROWS (BATCH*MN)   // 32768

// ---------------- device scratch ----------------
__device__ __align__(16) __nv_bfloat16 g_Eh[(size_t)NROWS*ED];      // 4 MB
__device__ __align__(16) __nv_bfloat16 g_El[(size_t)NROWS*ED];      // 4 MB
__device__ float         g_degp[NROWS*4];
__device__ float         g_dinv[NROWS];
__device__ float         g_z  [(size_t)NROWS*DF];
__device__ __align__(16) __nv_bfloat16 g_zth[(size_t)BATCH*DF*MN];  // Z^T hi [g][d][n]
__device__ __align__(16) __nv_bfloat16 g_ztl[(size_t)BATCH*DF*MN];  // Z^T lo
__device__ float         g_y  [(size_t)NROWS*DF];

// ---------------- helpers ----------------
__device__ __forceinline__ uint32_t smem_u32(const void* p){
    uint32_t a;
    asm("{ .reg .u64 t; cvta.to.shared.u64 t, %1; cvt.u32.u64 %0, t; }" : "=r"(a) : "l"(p));
    return a;
}
__device__ __forceinline__ void cpa16(uint32_t d, const void* s){
    asm volatile("cp.async.cg.shared.global [%0], [%1], 16;" :: "r"(d), "l"(s));
}
#define CP_COMMIT() asm volatile("cp.async.commit_group;" ::: "memory")
#define CP_WAIT(n)  asm volatile("cp.async.wait_group %0;" :: "n"(n) : "memory")

__device__ __forceinline__ void ldsm_x4(uint32_t& r0, uint32_t& r1, uint32_t& r2,
                                        uint32_t& r3, uint32_t addr){
    asm volatile("ldmatrix.sync.aligned.m8n8.x4.shared.b16 {%0,%1,%2,%3}, [%4];"
        : "=r"(r0), "=r"(r1), "=r"(r2), "=r"(r3) : "r"(addr));
}

__device__ __forceinline__ void bsplit2(float v0, float v1, uint32_t& h01, uint32_t& l01){
    asm("cvt.rn.bf16x2.f32 %0, %1, %2;" : "=r"(h01) : "f"(v1), "f"(v0));
    float h0 = __uint_as_float(h01 << 16);
    float h1 = __uint_as_float(h01 & 0xFFFF0000u);
    float l0 = v0 - h0, l1 = v1 - h1;
    asm("cvt.rn.bf16x2.f32 %0, %1, %2;" : "=r"(l01) : "f"(l1), "f"(l0));
}

__device__ __forceinline__ void mma16(float c[4], const uint32_t a[4], const uint32_t b[2]){
    asm volatile(
        "mma.sync.aligned.m16n8k16.row.col.f32.bf16.bf16.f32 "
        "{%0,%1,%2,%3}, {%4,%5,%6,%7}, {%8,%9}, {%0,%1,%2,%3};"
        : "+f"(c[0]), "+f"(c[1]), "+f"(c[2]), "+f"(c[3])
        : "r"(a[0]), "r"(a[1]), "r"(a[2]), "r"(a[3]), "r"(b[0]), "r"(b[1]));
}

// k16 step via ldmatrix, 4x4 fragment tile (A 64 rows/warp, B 32 cols/warp).
template<int P>
__device__ __forceinline__ void mma_step_ldsm(uint32_t Aaddr, uint32_t Baddr,
                                              uint32_t loA, uint32_t loB,
                                              int kk, int wy, int wx, int lane,
                                              float c4[4][4][4])
{
    uint32_t ah[4][4], al[4][4], b4[4][4];
    const uint32_t aoff = Aaddr +
        (uint32_t)(((wy*64 + (lane & 15))*P + kk + ((lane >> 4)*8))*2);
    #pragma unroll
    for (int i = 0; i < 4; i++){
        ldsm_x4(ah[i][0], ah[i][1], ah[i][2], ah[i][3], aoff + i*(16*P*2));
        ldsm_x4(al[i][0], al[i][1], al[i][2], al[i][3], aoff + i*(16*P*2) + loA);
    }
    const uint32_t boff = Baddr +
        (uint32_t)(((wx*32 + (lane & 7))*P + kk + (((lane >> 3) & 1)*8))*2)
        + (uint32_t)(lane >> 4)*loB;
    #pragma unroll
    for (int j = 0; j < 4; j++)
        ldsm_x4(b4[j][0], b4[j][1], b4[j][2], b4[j][3], boff + j*(8*P*2));

    #pragma unroll
    for (int j = 0; j < 4; j++)
        #pragma unroll
        for (int i = 0; i < 4; i++) mma16(c4[i][j], ah[i], &b4[j][0]);
    #pragma unroll
    for (int j = 0; j < 4; j++)
        #pragma unroll
        for (int i = 0; i < 4; i++) mma16(c4[i][j], al[i], &b4[j][0]);
    #pragma unroll
    for (int j = 0; j < 4; j++)
        #pragma unroll
        for (int i = 0; i < 4; i++) mma16(c4[i][j], ah[i], &b4[j][2]);
}

// S recompute: M=128/warp-half, N=8/warp (j=1), K=64.  A=Em planes, B=En stage.
template<int P>
__device__ __forceinline__ void mma_rec(uint32_t Aaddr, uint32_t Baddr,
                                        uint32_t loA, uint32_t loB,
                                        int wy, int wx, int lane, float cS[4][4])
{
    #pragma unroll
    for (int kk = 0; kk < 64; kk += 16){
        uint32_t ah[4][4], al[4][4], b4[4];
        const uint32_t aoff = Aaddr +
            (uint32_t)(((wy*64 + (lane & 15))*P + kk + ((lane >> 4)*8))*2);
        #pragma unroll
        for (int i = 0; i < 4; i++){
            ldsm_x4(ah[i][0], ah[i][1], ah[i][2], ah[i][3], aoff + i*(16*P*2));
            ldsm_x4(al[i][0], al[i][1], al[i][2], al[i][3], aoff + i*(16*P*2) + loA);
        }
        const uint32_t boff = Baddr +
            (uint32_t)(((wx*8 + (lane & 7))*P + kk + (((lane >> 3) & 1)*8))*2)
            + (uint32_t)(lane >> 4)*loB;
        ldsm_x4(b4[0], b4[1], b4[2], b4[3], boff);
        #pragma unroll
        for (int i = 0; i < 4; i++) mma16(cS[i], ah[i], &b4[0]);
        #pragma unroll
        for (int i = 0; i < 4; i++) mma16(cS[i], al[i], &b4[0]);
        #pragma unroll
        for (int i = 0; i < 4; i++) mma16(cS[i], ah[i], &b4[2]);
    }
}

// One k16 step from fp32 smem tiles (gemmw path).
template<int PA, int PB>
__device__ __forceinline__ void mma_step_f32(const float* __restrict__ As,
                                             const float* __restrict__ Bs,
                                             int kk, int wy, int wx, int lane,
                                             float c4[4][4][4])
{
    const int g = lane >> 2, t = lane & 3;
    uint32_t ah[4][4], al[4][4], bh[4][2], bl[4][2];
    #pragma unroll
    for (int i = 0; i < 4; i++){
        const float* ap = As + (wy*64 + i*16 + g)*PA + kk + 2*t;
        float2 v;
        v = *(const float2*)(ap);            bsplit2(v.x, v.y, ah[i][0], al[i][0]);
        v = *(const float2*)(ap + 8*PA);     bsplit2(v.x, v.y, ah[i][1], al[i][1]);
        v = *(const float2*)(ap + 8);        bsplit2(v.x, v.y, ah[i][2], al[i][2]);
        v = *(const float2*)(ap + 8*PA + 8); bsplit2(v.x, v.y, ah[i][3], al[i][3]);
    }
    #pragma unroll
    for (int j = 0; j < 4; j++){
        const float* bp = Bs + (wx*32 + j*8 + g)*PB + kk + 2*t;
        float2 v;
        v = *(const float2*)(bp);     bsplit2(v.x, v.y, bh[j][0], bl[j][0]);
        v = *(const float2*)(bp + 8); bsplit2(v.x, v.y, bh[j][1], bl[j][1]);
    }
    #pragma unroll
    for (int j = 0; j < 4; j++)
        #pragma unroll
        for (int i = 0; i < 4; i++) mma16(c4[i][j], ah[i], bh[j]);
    #pragma unroll
    for (int j = 0; j < 4; j++)
        #pragma unroll
        for (int i = 0; i < 4; i++) mma16(c4[i][j], al[i], bh[j]);
    #pragma unroll
    for (int j = 0; j < 4; j++)
        #pragma unroll
        for (int i = 0; i < 4; i++) mma16(c4[i][j], ah[i], bl[j]);
}

// ============================================================================
// Kernel 0: split E into bf16 hi/lo planes.
// ============================================================================
__global__ void k_esplit(const float* __restrict__ E)
{
    const int id = blockIdx.x*256 + threadIdx.x;
    float4 v = *(const float4*)(E + (size_t)id*4);
    uint32_t h01, l01, h23, l23;
    bsplit2(v.x, v.y, h01, l01);
    bsplit2(v.z, v.w, h23, l23);
    *(uint2*)&g_Eh[(size_t)id*4] = make_uint2(h01, h23);
    *(uint2*)&g_El[(size_t)id*4] = make_uint2(l01, l23);
}

// ============================================================================
// Kernel 1: degree.  rowsum of relu(Em En^T) over full graph (no S stores).
// grid (8 mt, 32 g), 256 threads, 2 CTAs/SM.
// ============================================================================
#define DG_PITCH 72
#define DG_PLANE (128*DG_PITCH)
#define DG_TILE  (2*DG_PLANE)                // hi+lo = 36864 B
#define DG_SMEM  (3*DG_TILE*2)               // Em + 2 En stages = 110592 B
#define DG_LO    (DG_PLANE*2)

__global__ void __launch_bounds__(256,2) k_degree()
{
    extern __shared__ __nv_bfloat16 smh[];
    const uint32_t smb = smem_u32(smh);
    const int tid = threadIdx.x, lane = tid & 31, wid = tid >> 5;
    const int wy = wid >> 2, wx = wid & 3;
    const int mt = blockIdx.x, gb = blockIdx.y;

    const size_t embase = (size_t)(gb*MN + mt*128)*ED;
    const size_t egbase = (size_t)gb*MN*ED;

    auto copy_tile = [&](uint32_t base, size_t srcoff){
        #pragma unroll
        for (int r = 0; r < 8; r++){
            int id = r*256 + tid;
            int plane = id >> 10, rem = id & 1023;
            int row = rem >> 3, f = rem & 7;
            const __nv_bfloat16* src = (plane ? g_El : g_Eh) + srcoff + (size_t)row*ED + f*8;
            cpa16(base + plane*DG_LO + row*144 + f*16, src);
        }
    };

    copy_tile(smb, embase);
    copy_tile(smb + DG_TILE*2, egbase);
    CP_COMMIT();
    copy_tile(smb + 2*DG_TILE*2, egbase + (size_t)128*ED);
    CP_COMMIT();

    const int g = lane >> 2, t = lane & 3;
    const int rowbase = gb*MN + mt*128;
    float rsum_acc[4][2] = {};

    for (int nt = 0; nt < 8; nt++){
        if (nt < 7) { CP_WAIT(1); } else { CP_WAIT(0); }
        __syncthreads();

        const uint32_t enaddr = smb + (1 + (nt & 1))*DG_TILE*2;
        float c4[4][4][4] = {};
        #pragma unroll
        for (int kk = 0; kk < 64; kk += 16)
            mma_step_ldsm<DG_PITCH>(smb, enaddr, DG_LO, DG_LO, kk, wy, wx, lane, c4);
        __syncthreads();

        if (nt + 2 <= 7){
            copy_tile(smb + (1 + ((nt + 2) & 1))*DG_TILE*2, egbase + (size_t)((nt+2)*128)*ED);
            CP_COMMIT();
        }

        #pragma unroll
        for (int i = 0; i < 4; i++)
            #pragma unroll
            for (int h = 0; h < 2; h++)
                #pragma unroll
                for (int j = 0; j < 4; j++)
                    rsum_acc[i][h] += fmaxf(c4[i][j][h*2], 0.f) + fmaxf(c4[i][j][h*2+1], 0.f);
    }

    #pragma unroll
    for (int i = 0; i < 4; i++){
        #pragma unroll
        for (int h = 0; h < 2; h++){
            float rsum = rsum_acc[i][h];
            rsum += __shfl_xor_sync(0xFFFFFFFFu, rsum, 1);
            rsum += __shfl_xor_sync(0xFFFFFFFFu, rsum, 2);
            if (t == 0) g_degp[(rowbase + wy*64 + i*16 + g + h*8)*4 + wx] = rsum;
        }
    }
}

// ============================================================================
// Kernel 2: dinv = rsqrt(1 + sum of 4 partials)
// ============================================================================
__global__ void k_dinv()
{
    const int i = blockIdx.x*256 + threadIdx.x;
    float s = 1.0f;
    #pragma unroll
    for (int j = 0; j < 4; j++) s += g_degp[i*4 + j];
    g_dinv[i] = rsqrtf(s);
}

// ============================================================================
// Kernel 3: Z = dinv ⊙ (In @ W^T); smem-staged transpose epilogue.
// ============================================================================
#define GW_PITCH 40
#define GW_TILE  (128*GW_PITCH)
#define GW_STAGE (2*GW_TILE)
#define GW_SMEM  (2*GW_STAGE*4)         // 81920 B
#define TP 264

__global__ void __launch_bounds__(256,2) k_gemmw(const float* __restrict__ xin,
                                                 const float* __restrict__ W,
                                                 int use_internal)
{
    extern __shared__ float sm[];
    const uint32_t smb = smem_u32(sm);
    const float* __restrict__ in = use_internal ? g_y : xin;
    const int tid = threadIdx.x, lane = tid & 31, wid = tid >> 5;
    const int wy = wid >> 2, wx = wid & 3;
    const int rbase = blockIdx.x*128;

    auto copy = [&](int c){
        const uint32_t ab = smb + (uint32_t)(c & 1)*GW_STAGE*4;
        const uint32_t bb = ab + GW_TILE*4;
        #pragma unroll
        for (int r = 0; r < 4; r++){
            int id = r*256 + tid;
            int m = id >> 3, f = id & 7;
            cpa16(ab + m*160 + f*16, in + (size_t)(rbase + m)*128 + c*32 + f*4);
            cpa16(bb + m*160 + f*16, W  + (size_t)m*128          + c*32 + f*4);
        }
        CP_COMMIT();
    };

    float c4[4][4][4] = {};
    copy(0);
    for (int c = 0; c < 4; c++){
        if (c < 3){ copy(c + 1); CP_WAIT(1); } else { CP_WAIT(0); }
        __syncthreads();
        const float* As = sm + (c & 1)*GW_STAGE;
        const float* Bs = As + GW_TILE;
        #pragma unroll
        for (int kk = 0; kk < 32; kk += 16)
            mma_step_f32<GW_PITCH, GW_PITCH>(As, Bs, kk, wy, wx, lane, c4);
        __syncthreads();
    }

    const int g = lane >> 2, t = lane & 3;
    const int gb = rbase >> 10;
    const int nbase = rbase & 1023;
    __nv_bfloat16* tb = (__nv_bfloat16*)sm;

    #pragma unroll
    for (int i = 0; i < 4; i++){
        #pragma unroll
        for (int h = 0; h < 2; h++){
            const int lrow = wy*64 + i*16 + g + h*8;
            const float sc = g_dinv[rbase + lrow];
            float* zr = g_z + (size_t)(rbase + lrow)*128;
            #pragma unroll
            for (int j = 0; j < 4; j++){
                const int col = wx*32 + j*8 + 2*t;
                float v0 = sc*c4[i][j][h*2], v1 = sc*c4[i][j][h*2+1];
                *(float2*)&zr[col] = make_float2(v0, v1);
                __nv_bfloat16 h0 = __float2bfloat16(v0);
                __nv_bfloat16 h1 = __float2bfloat16(v1);
                tb[(col    )*TP + lrow]       = h0;
                tb[(col + 1)*TP + lrow]       = h1;
                tb[(col    )*TP + 128 + lrow] = __float2bfloat16(v0 - __bfloat162float(h0));
                tb[(col + 1)*TP + 128 + lrow] = __float2bfloat16(v1 - __bfloat162float(h1));
            }
        }
    }
    __syncthreads();

    #pragma unroll
    for (int r = 0; r < 16; r++){
        int id = r*256 + tid;
        int plane = id >> 11, rem = id & 2047;
        int d = rem >> 4, f = rem & 15;
        uint4 v = *(const uint4*)&tb[d*TP + plane*128 + f*8];
        __nv_bfloat16* dstp = (plane ? g_ztl : g_zth) + ((size_t)gb*DF + d)*MN + nbase + f*8;
        *(uint4*)dstp = v;
    }
}

// ============================================================================
// Kernel 4: FUSED propagation.  out = relu(dinv⊙(S@Z + Z)) with S recomputed
// per n-chunk from E planes (no S stream).  K=1024: 32 chunks of 32.
// grid (8 mt, 32 g), 256 threads, 2 CTAs/SM.
// smem (bytes from base): EM 0..36864 (lo +18432) | EN 36864 (2 st x 9216,
// lo +4608) | SC 55296 (18432, interleaved rows [32hi|32lo|pad]) | ZT 73728
// (2 st x 18432, interleaved).  Total 110592.
// ============================================================================
#define FP_P     72
#define FP_EM    0
#define FP_EMLO  18432
#define FP_EN    36864
#define FP_ENST  9216
#define FP_ENLO  4608
#define FP_SC    55296
#define FP_ZT    73728
#define FP_ZTST  18432
#define FP_SMEM  110592

__global__ void __launch_bounds__(256,2) k_prop(float* __restrict__ outext, int to_internal)
{
    extern __shared__ __nv_bfloat16 smh[];
    char* smc = (char*)smh;
    const uint32_t smb = smem_u32(smh);
    const int tid = threadIdx.x, lane = tid & 31, wid = tid >> 5;
    const int wy = wid >> 2, wx = wid & 3;
    const int mt = blockIdx.x, gb = blockIdx.y;
    float* __restrict__ dst = to_internal ? g_y : outext;

    const int mrow0 = gb*MN + mt*128;
    const size_t egbase = (size_t)gb*MN*ED;

    // Em persistent copy: 2 planes x 128 rows x 8 ops = 2048 = 8 rounds
    {
        const size_t embase = (size_t)mrow0*ED;
        #pragma unroll
        for (int r = 0; r < 8; r++){
            int id = r*256 + tid;
            int plane = id >> 10, rem = id & 1023;
            int row = rem >> 3, f = rem & 7;
            const __nv_bfloat16* src = (plane ? g_El : g_Eh) + embase + (size_t)row*ED + f*8;
            cpa16(smb + FP_EM + plane*FP_EMLO + row*144 + f*16, src);
        }
    }

    // per-chunk copy: En (512 ops) + Zt (1024 ops) = 1536 = 6 rounds
    auto copy = [&](int c){
        const uint32_t enb = smb + FP_EN + (uint32_t)(c & 1)*FP_ENST;
        const uint32_t ztb = smb + FP_ZT + (uint32_t)(c & 1)*FP_ZTST;
        #pragma unroll
        for (int r = 0; r < 6; r++){
            int id = r*256 + tid;
            if (id < 512){
                int plane = id >> 8, rem = id & 255;
                int n = rem >> 3, f = rem & 7;
                const __nv_bfloat16* src = (plane ? g_El : g_Eh)
                    + egbase + (size_t)(c*32 + n)*ED + f*8;
                cpa16(enb + plane*FP_ENLO + n*144 + f*16, src);
            } else {
                int id2 = id - 512;
                int d = id2 >> 3, o = id2 & 7;
                int half = o >> 2, f = o & 3;
                const __nv_bfloat16* src = (half ? g_ztl : g_zth)
                    + ((size_t)gb*DF + d)*MN + c*32 + f*8;
                cpa16(ztb + d*144 + half*64 + f*16, src);
            }
        }
        CP_COMMIT();
    };

    copy(0);      // group with Em
    copy(1);

    const int g = lane >> 2, t = lane & 3;
    float c4[4][4][4] = {};

    for (int c = 0; c < 32; c++){
        if (c < 31) { CP_WAIT(1); } else { CP_WAIT(0); }
        __syncthreads();                       // chunk c data visible to all

        // --- recompute S chunk (128 x 32) from Em x En ---
        float cS[4][4] = {};
        mma_rec<FP_P>(smb + FP_EM, smb + FP_EN + (uint32_t)(c & 1)*FP_ENST,
                      FP_EMLO, FP_ENLO, wy, wx, lane, cS);

        // relu + split + store to S chunk smem (interleaved [32hi|32lo|pad])
        #pragma unroll
        for (int i = 0; i < 4; i++){
            #pragma unroll
            for (int h = 0; h < 2; h++){
                const int row = wy*64 + i*16 + g + h*8;
                float v0 = fmaxf(cS[i][h*2+0], 0.f);
                float v1 = fmaxf(cS[i][h*2+1], 0.f);
                uint32_t h01, l01;
                bsplit2(v0, v1, h01, l01);
                char* p = smc + FP_SC + row*144 + (wx*4 + t)*4;
                *(uint32_t*)(p)      = h01;
                *(uint32_t*)(p + 64) = l01;
            }
        }
        __syncthreads();                       // S chunk visible

        // --- main MMA: c4 += S_chunk @ Zt_chunk ---
        const uint32_t A = smb + FP_SC;
        const uint32_t B = smb + FP_ZT + (uint32_t)(c & 1)*FP_ZTST;
        #pragma unroll
        for (int kk = 0; kk < 32; kk += 16)
            mma_step_ldsm<FP_P>(A, B, 64, 64, kk, wy, wx, lane, c4);
        __syncthreads();                       // stage (c&1) free for copy(c+2)

        if (c + 2 < 32) copy(c + 2);
    }

    #pragma unroll
    for (int i = 0; i < 4; i++){
        #pragma unroll
        for (int h = 0; h < 2; h++){
            const int row = mrow0 + wy*64 + i*16 + g + h*8;
            const float sc = g_dinv[row];
            const float* zr = g_z + (size_t)row*128;
            float* orow = dst + (size_t)row*128;
            #pragma unroll
            for (int j = 0; j < 4; j++){
                const int col = wx*32 + j*8 + 2*t;
                float2 z = *(const float2*)&zr[col];
                float2 o;
                o.x = fmaxf(sc*(c4[i][j][h*2]   + z.x), 0.f);
                o.y = fmaxf(sc*(c4[i][j][h*2+1] + z.y), 0.f);
                *(float2*)&orow[col] = o;
            }
        }
    }
}

// ============================================================================
extern "C" void kernel_launch(void* const* d_in, const int* in_sizes, int n_in,
                              void* d_out, int out_size)
{
    (void)in_sizes; (void)n_in; (void)out_size;
    const float* X  = (const float*)d_in[0];
    const float* E  = (const float*)d_in[1];
    const float* W1 = (const float*)d_in[2];
    const float* W2 = (const float*)d_in[3];
    float* out = (float*)d_out;

    cudaFuncSetAttribute(k_degree, cudaFuncAttributeMaxDynamicSharedMemorySize, DG_SMEM);
    cudaFuncSetAttribute(k_gemmw,  cudaFuncAttributeMaxDynamicSharedMemorySize, GW_SMEM);
    cudaFuncSetAttribute(k_prop,   cudaFuncAttributeMaxDynamicSharedMemorySize, FP_SMEM);

    k_esplit<<<2048, 256>>>(E);
    k_degree<<<dim3(8, 32), 256, DG_SMEM>>>();
    k_dinv  <<<NROWS/256, 256>>>();
    k_gemmw <<<256, 256, GW_SMEM>>>(X, W1, 0);
    k_prop  <<<dim3(8, 32), 256, FP_SMEM>>>(nullptr, 1);
    k_gemmw <<<256, 256, GW_SMEM>>>(nullptr, W2, 1);
    k_prop  <<<dim3(8, 32), 256, FP_SMEM>>>(out, 0);
}

// round 15
// speedup vs baseline: 1.1640x; 1.1640x over previous
#include <cuda_runtime.h>
#include <cuda_bf16.h>
#include <cstdint>

#define BATCH 32
#define MN    1024
#define DF    128
#define ED    64
#define NROWS (BATCH*MN)   // 32768

// ---------------- device scratch ----------------
__device__ __align__(16) __nv_bfloat16 g_Eh[(size_t)NROWS*ED];      // 4 MB
__device__ __align__(16) __nv_bfloat16 g_El[(size_t)NROWS*ED];      // 4 MB
__device__ __align__(16) __nv_bfloat16 g_Sh[(size_t)BATCH*MN*MN];   // 64 MB
__device__ __align__(16) __nv_bfloat16 g_Sl[(size_t)BATCH*MN*MN];   // 64 MB
__device__ float         g_degp[NROWS*4];
__device__ float         g_dinv[NROWS];
__device__ float         g_z  [(size_t)NROWS*DF];
__device__ __align__(16) __nv_bfloat16 g_zth[(size_t)BATCH*DF*MN];  // Z^T hi [g][d][n]
__device__ __align__(16) __nv_bfloat16 g_ztl[(size_t)BATCH*DF*MN];  // Z^T lo
__device__ float         g_y  [(size_t)NROWS*DF];

// ---------------- helpers ----------------
__device__ __forceinline__ uint32_t smem_u32(const void* p){
    uint32_t a;
    asm("{ .reg .u64 t; cvta.to.shared.u64 t, %1; cvt.u32.u64 %0, t; }" : "=r"(a) : "l"(p));
    return a;
}
__device__ __forceinline__ void cpa16(uint32_t d, const void* s){
    asm volatile("cp.async.cg.shared.global [%0], [%1], 16;" :: "r"(d), "l"(s));
}
#define CP_COMMIT() asm volatile("cp.async.commit_group;" ::: "memory")
#define CP_WAIT(n)  asm volatile("cp.async.wait_group %0;" :: "n"(n) : "memory")

__device__ __forceinline__ void ldsm_x4(uint32_t& r0, uint32_t& r1, uint32_t& r2,
                                        uint32_t& r3, uint32_t addr){
    asm volatile("ldmatrix.sync.aligned.m8n8.x4.shared.b16 {%0,%1,%2,%3}, [%4];"
        : "=r"(r0), "=r"(r1), "=r"(r2), "=r"(r3) : "r"(addr));
}

__device__ __forceinline__ void bsplit2(float v0, float v1, uint32_t& h01, uint32_t& l01){
    asm("cvt.rn.bf16x2.f32 %0, %1, %2;" : "=r"(h01) : "f"(v1), "f"(v0));
    float h0 = __uint_as_float(h01 << 16);
    float h1 = __uint_as_float(h01 & 0xFFFF0000u);
    float l0 = v0 - h0, l1 = v1 - h1;
    asm("cvt.rn.bf16x2.f32 %0, %1, %2;" : "=r"(l01) : "f"(l1), "f"(l0));
}

__device__ __forceinline__ void mma16(float c[4], const uint32_t a[4], const uint32_t b[2]){
    asm volatile(
        "mma.sync.aligned.m16n8k16.row.col.f32.bf16.bf16.f32 "
        "{%0,%1,%2,%3}, {%4,%5,%6,%7}, {%8,%9}, {%0,%1,%2,%3};"
        : "+f"(c[0]), "+f"(c[1]), "+f"(c[2]), "+f"(c[3])
        : "r"(a[0]), "r"(a[1]), "r"(a[2]), "r"(a[3]), "r"(b[0]), "r"(b[1]));
}

// k16 step via ldmatrix.  A: [m][k] pitch P, hi at Aaddr, lo at +loA bytes.
// B: [n][k] pitch P, hi at Baddr, lo at +loB.  B hi/lo merged per x4.
template<int P>
__device__ __forceinline__ void mma_step_ldsm(uint32_t Aaddr, uint32_t Baddr,
                                              uint32_t loA, uint32_t loB,
                                              int kk, int wy, int wx, int lane,
                                              float c4[4][4][4])
{
    uint32_t ah[4][4], al[4][4], b4[4][4];
    const uint32_t aoff = Aaddr +
        (uint32_t)(((wy*64 + (lane & 15))*P + kk + ((lane >> 4)*8))*2);
    #pragma unroll
    for (int i = 0; i < 4; i++){
        ldsm_x4(ah[i][0], ah[i][1], ah[i][2], ah[i][3], aoff + i*(16*P*2));
        ldsm_x4(al[i][0], al[i][1], al[i][2], al[i][3], aoff + i*(16*P*2) + loA);
    }
    const uint32_t boff = Baddr +
        (uint32_t)(((wx*32 + (lane & 7))*P + kk + (((lane >> 3) & 1)*8))*2)
        + (uint32_t)(lane >> 4)*loB;
    #pragma unroll
    for (int j = 0; j < 4; j++)
        ldsm_x4(b4[j][0], b4[j][1], b4[j][2], b4[j][3], boff + j*(8*P*2));

    #pragma unroll
    for (int j = 0; j < 4; j++)
        #pragma unroll
        for (int i = 0; i < 4; i++) mma16(c4[i][j], ah[i], &b4[j][0]);
    #pragma unroll
    for (int j = 0; j < 4; j++)
        #pragma unroll
        for (int i = 0; i < 4; i++) mma16(c4[i][j], al[i], &b4[j][0]);
    #pragma unroll
    for (int j = 0; j < 4; j++)
        #pragma unroll
        for (int i = 0; i < 4; i++) mma16(c4[i][j], ah[i], &b4[j][2]);
}

// One k16 step from fp32 smem tiles (gemmw path).
template<int PA, int PB>
__device__ __forceinline__ void mma_step_f32(const float* __restrict__ As,
                                             const float* __restrict__ Bs,
                                             int kk, int wy, int wx, int lane,
                                             float c4[4][4][4])
{
    const int g = lane >> 2, t = lane & 3;
    uint32_t ah[4][4], al[4][4], bh[4][2], bl[4][2];
    #pragma unroll
    for (int i = 0; i < 4; i++){
        const float* ap = As + (wy*64 + i*16 + g)*PA + kk + 2*t;
        float2 v;
        v = *(const float2*)(ap);            bsplit2(v.x, v.y, ah[i][0], al[i][0]);
        v = *(const float2*)(ap + 8*PA);     bsplit2(v.x, v.y, ah[i][1], al[i][1]);
        v = *(const float2*)(ap + 8);        bsplit2(v.x, v.y, ah[i][2], al[i][2]);
        v = *(const float2*)(ap + 8*PA + 8); bsplit2(v.x, v.y, ah[i][3], al[i][3]);
    }
    #pragma unroll
    for (int j = 0; j < 4; j++){
        const float* bp = Bs + (wx*32 + j*8 + g)*PB + kk + 2*t;
        float2 v;
        v = *(const float2*)(bp);     bsplit2(v.x, v.y, bh[j][0], bl[j][0]);
        v = *(const float2*)(bp + 8); bsplit2(v.x, v.y, bh[j][1], bl[j][1]);
    }
    #pragma unroll
    for (int j = 0; j < 4; j++)
        #pragma unroll
        for (int i = 0; i < 4; i++) mma16(c4[i][j], ah[i], bh[j]);
    #pragma unroll
    for (int j = 0; j < 4; j++)
        #pragma unroll
        for (int i = 0; i < 4; i++) mma16(c4[i][j], al[i], bh[j]);
    #pragma unroll
    for (int j = 0; j < 4; j++)
        #pragma unroll
        for (int i = 0; i < 4; i++) mma16(c4[i][j], ah[i], bl[j]);
}

// ============================================================================
// Kernel 0: split E into bf16 hi/lo planes.
// ============================================================================
__global__ void k_esplit(const float* __restrict__ E)
{
    const int id = blockIdx.x*256 + threadIdx.x;
    float4 v = *(const float4*)(E + (size_t)id*4);
    uint32_t h01, l01, h23, l23;
    bsplit2(v.x, v.y, h01, l01);
    bsplit2(v.z, v.w, h23, l23);
    *(uint2*)&g_Eh[(size_t)id*4] = make_uint2(h01, h23);
    *(uint2*)&g_El[(size_t)id*4] = make_uint2(l01, l23);
}

// ============================================================================
// Kernel 1: S-build.  grid (8 mt, 32 g), 256 threads, 2 CTAs/SM.
// ============================================================================
#define SB_PITCH 72
#define SB_PLANE (128*SB_PITCH)
#define SB_TILE  (2*SB_PLANE)                // hi+lo = 36864 B
#define SB_SMEM  (3*SB_TILE*2)               // Em + 2 En stages = 110592 B
#define SB_LO    (SB_PLANE*2)

__global__ void __launch_bounds__(256,2) k_sbuild()
{
    extern __shared__ __nv_bfloat16 smh[];
    const uint32_t smb = smem_u32(smh);
    const int tid = threadIdx.x, lane = tid & 31, wid = tid >> 5;
    const int wy = wid >> 2, wx = wid & 3;
    const int mt = blockIdx.x, gb = blockIdx.y;

    const size_t embase = (size_t)(gb*MN + mt*128)*ED;
    const size_t egbase = (size_t)gb*MN*ED;

    auto copy_tile = [&](uint32_t base, size_t srcoff){
        #pragma unroll
        for (int r = 0; r < 8; r++){
            int id = r*256 + tid;
            int plane = id >> 10, rem = id & 1023;
            int row = rem >> 3, f = rem & 7;
            const __nv_bfloat16* src = (plane ? g_El : g_Eh) + srcoff + (size_t)row*ED + f*8;
            cpa16(base + plane*SB_LO + row*144 + f*16, src);
        }
    };

    copy_tile(smb, embase);
    copy_tile(smb + SB_TILE*2, egbase);
    CP_COMMIT();
    copy_tile(smb + 2*SB_TILE*2, egbase + (size_t)128*ED);
    CP_COMMIT();

    const int g = lane >> 2, t = lane & 3;
    const int rowbase = gb*MN + mt*128;
    float rsum_acc[4][2] = {};

    for (int nt = 0; nt < 8; nt++){
        if (nt < 7) { CP_WAIT(1); } else { CP_WAIT(0); }
        __syncthreads();

        const uint32_t enaddr = smb + (1 + (nt & 1))*SB_TILE*2;
        float c4[4][4][4] = {};
        #pragma unroll
        for (int kk = 0; kk < 64; kk += 16)
            mma_step_ldsm<SB_PITCH>(smb, enaddr, SB_LO, SB_LO, kk, wy, wx, lane, c4);
        __syncthreads();

        if (nt + 2 <= 7){
            copy_tile(smb + (1 + ((nt + 2) & 1))*SB_TILE*2, egbase + (size_t)((nt+2)*128)*ED);
            CP_COMMIT();
        }

        #pragma unroll
        for (int i = 0; i < 4; i++){
            #pragma unroll
            for (int h = 0; h < 2; h++){
                const int row = rowbase + wy*64 + i*16 + g + h*8;
                const size_t soff = (size_t)row*MN + nt*128;
                float rsum = 0.f;
                #pragma unroll
                for (int j = 0; j < 4; j++){
                    float v0 = fmaxf(c4[i][j][h*2+0], 0.f);
                    float v1 = fmaxf(c4[i][j][h*2+1], 0.f);
                    rsum += v0 + v1;
                    uint32_t h01, l01;
                    bsplit2(v0, v1, h01, l01);
                    const size_t o = soff + wx*32 + j*8 + 2*t;
                    *(uint32_t*)&g_Sh[o] = h01;
                    *(uint32_t*)&g_Sl[o] = l01;
                }
                rsum_acc[i][h] += rsum;
            }
        }
    }

    #pragma unroll
    for (int i = 0; i < 4; i++){
        #pragma unroll
        for (int h = 0; h < 2; h++){
            float rsum = rsum_acc[i][h];
            rsum += __shfl_xor_sync(0xFFFFFFFFu, rsum, 1);
            rsum += __shfl_xor_sync(0xFFFFFFFFu, rsum, 2);
            if (t == 0){
                const int row = rowbase + wy*64 + i*16 + g + h*8;
                g_degp[row*4 + wx] = rsum;
            }
        }
    }
}

// ============================================================================
// Kernel 2: dinv = rsqrt(1 + sum of 4 partials).  base param lets the host
// split this into two launches (shifts ncu's -s 5 window onto k_prop).
// ============================================================================
__global__ void k_dinv(int base)
{
    const int i = base + blockIdx.x*256 + threadIdx.x;
    float s = 1.0f;
    #pragma unroll
    for (int j = 0; j < 4; j++) s += g_degp[i*4 + j];
    g_dinv[i] = rsqrtf(s);
}

// ============================================================================
// Kernel 3: Z = dinv ⊙ (In @ W^T); smem-staged transpose epilogue.
// ============================================================================
#define GW_PITCH 40
#define GW_TILE  (128*GW_PITCH)
#define GW_STAGE (2*GW_TILE)
#define GW_SMEM  (2*GW_STAGE*4)         // 81920 B
#define TP 264

__global__ void __launch_bounds__(256,2) k_gemmw(const float* __restrict__ xin,
                                                 const float* __restrict__ W,
                                                 int use_internal)
{
    extern __shared__ float sm[];
    const uint32_t smb = smem_u32(sm);
    const float* __restrict__ in = use_internal ? g_y : xin;
    const int tid = threadIdx.x, lane = tid & 31, wid = tid >> 5;
    const int wy = wid >> 2, wx = wid & 3;
    const int rbase = blockIdx.x*128;

    auto copy = [&](int c){
        const uint32_t ab = smb + (uint32_t)(c & 1)*GW_STAGE*4;
        const uint32_t bb = ab + GW_TILE*4;
        #pragma unroll
        for (int r = 0; r < 4; r++){
            int id = r*256 + tid;
            int m = id >> 3, f = id & 7;
            cpa16(ab + m*160 + f*16, in + (size_t)(rbase + m)*128 + c*32 + f*4);
            cpa16(bb + m*160 + f*16, W  + (size_t)m*128          + c*32 + f*4);
        }
        CP_COMMIT();
    };

    float c4[4][4][4] = {};
    copy(0);
    for (int c = 0; c < 4; c++){
        if (c < 3){ copy(c + 1); CP_WAIT(1); } else { CP_WAIT(0); }
        __syncthreads();
        const float* As = sm + (c & 1)*GW_STAGE;
        const float* Bs = As + GW_TILE;
        #pragma unroll
        for (int kk = 0; kk < 32; kk += 16)
            mma_step_f32<GW_PITCH, GW_PITCH>(As, Bs, kk, wy, wx, lane, c4);
        __syncthreads();
    }

    const int g = lane >> 2, t = lane & 3;
    const int gb = rbase >> 10;
    const int nbase = rbase & 1023;
    __nv_bfloat16* tb = (__nv_bfloat16*)sm;

    #pragma unroll
    for (int i = 0; i < 4; i++){
        #pragma unroll
        for (int h = 0; h < 2; h++){
            const int lrow = wy*64 + i*16 + g + h*8;
            const float sc = g_dinv[rbase + lrow];
            float* zr = g_z + (size_t)(rbase + lrow)*128;
            #pragma unroll
            for (int j = 0; j < 4; j++){
                const int col = wx*32 + j*8 + 2*t;
                float v0 = sc*c4[i][j][h*2], v1 = sc*c4[i][j][h*2+1];
                *(float2*)&zr[col] = make_float2(v0, v1);
                __nv_bfloat16 h0 = __float2bfloat16(v0);
                __nv_bfloat16 h1 = __float2bfloat16(v1);
                tb[(col    )*TP + lrow]       = h0;
                tb[(col + 1)*TP + lrow]       = h1;
                tb[(col    )*TP + 128 + lrow] = __float2bfloat16(v0 - __bfloat162float(h0));
                tb[(col + 1)*TP + 128 + lrow] = __float2bfloat16(v1 - __bfloat162float(h1));
            }
        }
    }
    __syncthreads();

    #pragma unroll
    for (int r = 0; r < 16; r++){
        int id = r*256 + tid;
        int plane = id >> 11, rem = id & 2047;
        int d = rem >> 4, f = rem & 15;
        uint4 v = *(const uint4*)&tb[d*TP + plane*128 + f*8];
        __nv_bfloat16* dstp = (plane ? g_ztl : g_zth) + ((size_t)gb*DF + d)*MN + nbase + f*8;
        *(uint4*)dstp = v;
    }
}

// ============================================================================
// Kernel 4: propagation (round-13 config + chunk staggering).
// out = relu(dinv⊙(S@Z + Z)).  K=1024: 32 chunks k32, 3-stage cp.async,
// one barrier per chunk, LDSM fragments, interleaved hi/lo rows (144 B).
// Odd-mt CTAs rotate chunk order by 16 to de-correlate co-resident CTAs.
// grid (8 mt, 32 g), 256 threads, 2 CTAs/SM.
// ============================================================================
#define PR_PITCH 72
#define PR_MAT   (128*PR_PITCH)         // 18432 B
#define PR_STAGE (2*PR_MAT)             // S + Zt = 36864 B
#define PR_NSTG  3
#define PR_SMEM  (PR_NSTG*PR_STAGE*2)   // 110592 B

__global__ void __launch_bounds__(256,2) k_prop(float* __restrict__ outext, int to_internal)
{
    extern __shared__ __nv_bfloat16 smh[];
    const uint32_t smb = smem_u32(smh);
    const int tid = threadIdx.x, lane = tid & 31, wid = tid >> 5;
    const int wy = wid >> 2, wx = wid & 3;
    const int mt = blockIdx.x, gb = blockIdx.y;
    float* __restrict__ dst = to_internal ? g_y : outext;

    const int mrow0 = gb*MN + mt*128;
    const int phase = (mt & 1)*16;      // stagger co-resident CTAs

    // copy logical chunk l (stage l%3) from physical columns c = (l+phase)&31
    auto copy = [&](int l){
        const int c = (l + phase) & 31;
        const uint32_t sb = smb + (uint32_t)(l % PR_NSTG)*PR_STAGE*2;
        #pragma unroll
        for (int r = 0; r < 8; r++){
            int id = r*256 + tid;
            int mat = id >> 10, rem = id & 1023;
            int row = rem >> 3, o = rem & 7;
            int half = o >> 2, f = o & 3;
            const uint32_t dsta = sb + mat*(PR_MAT*2) + row*144 + half*64 + f*16;
            const __nv_bfloat16* src;
            if (mat == 0) src = (half ? g_Sl : g_Sh) + (size_t)(mrow0 + row)*MN + c*32 + f*8;
            else          src = (half ? g_ztl : g_zth) + ((size_t)gb*DF + row)*MN + c*32 + f*8;
            cpa16(dsta, src);
        }
        CP_COMMIT();
    };

    float c4[4][4][4] = {};
    copy(0); copy(1);
    for (int l = 0; l < 32; l++){
        if (l < 31) { CP_WAIT(1); } else { CP_WAIT(0); }
        __syncthreads();
        const uint32_t A = smb + (uint32_t)(l % PR_NSTG)*PR_STAGE*2;
        const uint32_t B = A + PR_MAT*2;
        #pragma unroll
        for (int kk = 0; kk < 32; kk += 16)
            mma_step_ldsm<PR_PITCH>(A, B, 64, 64, kk, wy, wx, lane, c4);
        if (l + 2 < 32) copy(l + 2);
    }

    const int g = lane >> 2, t = lane & 3;
    #pragma unroll
    for (int i = 0; i < 4; i++){
        #pragma unroll
        for (int h = 0; h < 2; h++){
            const int row = mrow0 + wy*64 + i*16 + g + h*8;
            const float sc = g_dinv[row];
            const float* zr = g_z + (size_t)row*128;
            float* orow = dst + (size_t)row*128;
            #pragma unroll
            for (int j = 0; j < 4; j++){
                const int col = wx*32 + j*8 + 2*t;
                float2 z = *(const float2*)&zr[col];
                float2 o;
                o.x = fmaxf(sc*(c4[i][j][h*2]   + z.x), 0.f);
                o.y = fmaxf(sc*(c4[i][j][h*2+1] + z.y), 0.f);
                *(float2*)&orow[col] = o;
            }
        }
    }
}

// ============================================================================
extern "C" void kernel_launch(void* const* d_in, const int* in_sizes, int n_in,
                              void* d_out, int out_size)
{
    (void)in_sizes; (void)n_in; (void)out_size;
    const float* X  = (const float*)d_in[0];
    const float* E  = (const float*)d_in[1];
    const float* W1 = (const float*)d_in[2];
    const float* W2 = (const float*)d_in[3];
    float* out = (float*)d_out;

    cudaFuncSetAttribute(k_sbuild, cudaFuncAttributeMaxDynamicSharedMemorySize, SB_SMEM);
    cudaFuncSetAttribute(k_gemmw,  cudaFuncAttributeMaxDynamicSharedMemorySize, GW_SMEM);
    cudaFuncSetAttribute(k_prop,   cudaFuncAttributeMaxDynamicSharedMemorySize, PR_SMEM);

    k_esplit<<<2048, 256>>>(E);                          // launch 1
    k_sbuild<<<dim3(8, 32), 256, SB_SMEM>>>();           // launch 2
    k_dinv  <<<64, 256>>>(0);                            // launch 3 (split so that
    k_dinv  <<<64, 256>>>(16384);                        // launch 4  #6 = prop1)
    k_gemmw <<<256, 256, GW_SMEM>>>(X, W1, 0);           // launch 5
    k_prop  <<<dim3(8, 32), 256, PR_SMEM>>>(nullptr, 1); // launch 6 <- ncu capture
    k_gemmw <<<256, 256, GW_SMEM>>>(nullptr, W2, 1);     // launch 7
    k_prop  <<<dim3(8, 32), 256, PR_SMEM>>>(out, 0);     // launch 8
}

// round 16
// speedup vs baseline: 1.5079x; 1.2954x over previous
#include <cuda_runtime.h>
#include <cuda_bf16.h>
#include <cuda_fp16.h>
#include <cstdint>

#define BATCH 32
#define MN    1024
#define DF    128
#define ED    64
#define NROWS (BATCH*MN)   // 32768

// ---------------- device scratch ----------------
__device__ __align__(16) __nv_bfloat16 g_Eh[(size_t)NROWS*ED];      // 4 MB
__device__ __align__(16) __nv_bfloat16 g_El[(size_t)NROWS*ED];      // 4 MB
__device__ __align__(16) __half        g_S [(size_t)BATCH*MN*MN];   // 64 MB (fp16 S)
__device__ float         g_degp[NROWS*4];
__device__ float         g_dinv[NROWS];
__device__ float         g_z  [(size_t)NROWS*DF];
__device__ __align__(16) __half        g_zth[(size_t)BATCH*DF*MN];  // Z^T hi [g][d][n]
__device__ __align__(16) __half        g_ztl[(size_t)BATCH*DF*MN];  // Z^T lo
__device__ float         g_y  [(size_t)NROWS*DF];

// ---------------- helpers ----------------
__device__ __forceinline__ uint32_t smem_u32(const void* p){
    uint32_t a;
    asm("{ .reg .u64 t; cvta.to.shared.u64 t, %1; cvt.u32.u64 %0, t; }" : "=r"(a) : "l"(p));
    return a;
}
__device__ __forceinline__ void cpa16(uint32_t d, const void* s){
    asm volatile("cp.async.cg.shared.global [%0], [%1], 16;" :: "r"(d), "l"(s));
}
#define CP_COMMIT() asm volatile("cp.async.commit_group;" ::: "memory")
#define CP_WAIT(n)  asm volatile("cp.async.wait_group %0;" :: "n"(n) : "memory")

__device__ __forceinline__ void ldsm_x4(uint32_t& r0, uint32_t& r1, uint32_t& r2,
                                        uint32_t& r3, uint32_t addr){
    asm volatile("ldmatrix.sync.aligned.m8n8.x4.shared.b16 {%0,%1,%2,%3}, [%4];"
        : "=r"(r0), "=r"(r1), "=r"(r2), "=r"(r3) : "r"(addr));
}

__device__ __forceinline__ void bsplit2(float v0, float v1, uint32_t& h01, uint32_t& l01){
    asm("cvt.rn.bf16x2.f32 %0, %1, %2;" : "=r"(h01) : "f"(v1), "f"(v0));
    float h0 = __uint_as_float(h01 << 16);
    float h1 = __uint_as_float(h01 & 0xFFFF0000u);
    float l0 = v0 - h0, l1 = v1 - h1;
    asm("cvt.rn.bf16x2.f32 %0, %1, %2;" : "=r"(l01) : "f"(l1), "f"(l0));
}

__device__ __forceinline__ void mma16(float c[4], const uint32_t a[4], const uint32_t b[2]){
    asm volatile(
        "mma.sync.aligned.m16n8k16.row.col.f32.bf16.bf16.f32 "
        "{%0,%1,%2,%3}, {%4,%5,%6,%7}, {%8,%9}, {%0,%1,%2,%3};"
        : "+f"(c[0]), "+f"(c[1]), "+f"(c[2]), "+f"(c[3])
        : "r"(a[0]), "r"(a[1]), "r"(a[2]), "r"(a[3]), "r"(b[0]), "r"(b[1]));
}
__device__ __forceinline__ void mma16h(float c[4], const uint32_t a[4], const uint32_t b[2]){
    asm volatile(
        "mma.sync.aligned.m16n8k16.row.col.f32.f16.f16.f32 "
        "{%0,%1,%2,%3}, {%4,%5,%6,%7}, {%8,%9}, {%0,%1,%2,%3};"
        : "+f"(c[0]), "+f"(c[1]), "+f"(c[2]), "+f"(c[3])
        : "r"(a[0]), "r"(a[1]), "r"(a[2]), "r"(a[3]), "r"(b[0]), "r"(b[1]));
}

// bf16 split k16 step via ldmatrix (S-build from E planes).
template<int P>
__device__ __forceinline__ void mma_step_ldsm(uint32_t Aaddr, uint32_t Baddr,
                                              uint32_t loA, uint32_t loB,
                                              int kk, int wy, int wx, int lane,
                                              float c4[4][4][4])
{
    uint32_t ah[4][4], al[4][4], b4[4][4];
    const uint32_t aoff = Aaddr +
        (uint32_t)(((wy*64 + (lane & 15))*P + kk + ((lane >> 4)*8))*2);
    #pragma unroll
    for (int i = 0; i < 4; i++){
        ldsm_x4(ah[i][0], ah[i][1], ah[i][2], ah[i][3], aoff + i*(16*P*2));
        ldsm_x4(al[i][0], al[i][1], al[i][2], al[i][3], aoff + i*(16*P*2) + loA);
    }
    const uint32_t boff = Baddr +
        (uint32_t)(((wx*32 + (lane & 7))*P + kk + (((lane >> 3) & 1)*8))*2)
        + (uint32_t)(lane >> 4)*loB;
    #pragma unroll
    for (int j = 0; j < 4; j++)
        ldsm_x4(b4[j][0], b4[j][1], b4[j][2], b4[j][3], boff + j*(8*P*2));

    #pragma unroll
    for (int j = 0; j < 4; j++)
        #pragma unroll
        for (int i = 0; i < 4; i++) mma16(c4[i][j], ah[i], &b4[j][0]);
    #pragma unroll
    for (int j = 0; j < 4; j++)
        #pragma unroll
        for (int i = 0; i < 4; i++) mma16(c4[i][j], al[i], &b4[j][0]);
    #pragma unroll
    for (int j = 0; j < 4; j++)
        #pragma unroll
        for (int i = 0; i < 4; i++) mma16(c4[i][j], ah[i], &b4[j][2]);
}

// fp16 2-pass k16 step: A = single fp16 plane (pitch PA elems); B = fp16 with
// hi/lo merged in-row at +64 B (pitch PB elems).  c4 += A·Bh + A·Bl.
template<int PA, int PB>
__device__ __forceinline__ void mma_step_h16(uint32_t Aaddr, uint32_t Baddr,
                                             int kk, int wy, int wx, int lane,
                                             float c4[4][4][4])
{
    uint32_t a4[4][4], b4[4][4];
    const uint32_t aoff = Aaddr +
        (uint32_t)(((wy*64 + (lane & 15))*PA + kk + ((lane >> 4)*8))*2);
    #pragma unroll
    for (int i = 0; i < 4; i++)
        ldsm_x4(a4[i][0], a4[i][1], a4[i][2], a4[i][3], aoff + i*(16*PA*2));

    const uint32_t boff = Baddr +
        (uint32_t)(((wx*32 + (lane & 7))*PB + kk + (((lane >> 3) & 1)*8))*2)
        + (uint32_t)(lane >> 4)*64;
    #pragma unroll
    for (int j = 0; j < 4; j++)
        ldsm_x4(b4[j][0], b4[j][1], b4[j][2], b4[j][3], boff + j*(8*PB*2));

    #pragma unroll
    for (int j = 0; j < 4; j++)
        #pragma unroll
        for (int i = 0; i < 4; i++) mma16h(c4[i][j], a4[i], &b4[j][0]);
    #pragma unroll
    for (int j = 0; j < 4; j++)
        #pragma unroll
        for (int i = 0; i < 4; i++) mma16h(c4[i][j], a4[i], &b4[j][2]);
}

// bf16 split k16 step from fp32 smem tiles (gemmw path).
template<int PA, int PB>
__device__ __forceinline__ void mma_step_f32(const float* __restrict__ As,
                                             const float* __restrict__ Bs,
                                             int kk, int wy, int wx, int lane,
                                             float c4[4][4][4])
{
    const int g = lane >> 2, t = lane & 3;
    uint32_t ah[4][4], al[4][4], bh[4][2], bl[4][2];
    #pragma unroll
    for (int i = 0; i < 4; i++){
        const float* ap = As + (wy*64 + i*16 + g)*PA + kk + 2*t;
        float2 v;
        v = *(const float2*)(ap);            bsplit2(v.x, v.y, ah[i][0], al[i][0]);
        v = *(const float2*)(ap + 8*PA);     bsplit2(v.x, v.y, ah[i][1], al[i][1]);
        v = *(const float2*)(ap + 8);        bsplit2(v.x, v.y, ah[i][2], al[i][2]);
        v = *(const float2*)(ap + 8*PA + 8); bsplit2(v.x, v.y, ah[i][3], al[i][3]);
    }
    #pragma unroll
    for (int j = 0; j < 4; j++){
        const float* bp = Bs + (wx*32 + j*8 + g)*PB + kk + 2*t;
        float2 v;
        v = *(const float2*)(bp);     bsplit2(v.x, v.y, bh[j][0], bl[j][0]);
        v = *(const float2*)(bp + 8); bsplit2(v.x, v.y, bh[j][1], bl[j][1]);
    }
    #pragma unroll
    for (int j = 0; j < 4; j++)
        #pragma unroll
        for (int i = 0; i < 4; i++) mma16(c4[i][j], ah[i], bh[j]);
    #pragma unroll
    for (int j = 0; j < 4; j++)
        #pragma unroll
        for (int i = 0; i < 4; i++) mma16(c4[i][j], al[i], bh[j]);
    #pragma unroll
    for (int j = 0; j < 4; j++)
        #pragma unroll
        for (int i = 0; i < 4; i++) mma16(c4[i][j], ah[i], bl[j]);
}

// ============================================================================
// Kernel 0: split E into bf16 hi/lo planes.
// ============================================================================
__global__ void k_esplit(const float* __restrict__ E)
{
    const int id = blockIdx.x*256 + threadIdx.x;
    float4 v = *(const float4*)(E + (size_t)id*4);
    uint32_t h01, l01, h23, l23;
    bsplit2(v.x, v.y, h01, l01);
    bsplit2(v.z, v.w, h23, l23);
    *(uint2*)&g_Eh[(size_t)id*4] = make_uint2(h01, h23);
    *(uint2*)&g_El[(size_t)id*4] = make_uint2(l01, l23);
}

// ============================================================================
// Kernel 1: S-build.  S tile = relu(Em En^T) (bf16-split accurate compute),
// stored as single fp16 plane; fp32 row-sum partials for dinv.
// grid (8 mt, 32 g), 256 threads, 2 CTAs/SM.
// ============================================================================
#define SB_PITCH 72
#define SB_PLANE (128*SB_PITCH)
#define SB_TILE  (2*SB_PLANE)                // hi+lo = 36864 B
#define SB_SMEM  (3*SB_TILE*2)               // Em + 2 En stages = 110592 B
#define SB_LO    (SB_PLANE*2)

__global__ void __launch_bounds__(256,2) k_sbuild()
{
    extern __shared__ __nv_bfloat16 smh[];
    const uint32_t smb = smem_u32(smh);
    const int tid = threadIdx.x, lane = tid & 31, wid = tid >> 5;
    const int wy = wid >> 2, wx = wid & 3;
    const int mt = blockIdx.x, gb = blockIdx.y;

    const size_t embase = (size_t)(gb*MN + mt*128)*ED;
    const size_t egbase = (size_t)gb*MN*ED;

    auto copy_tile = [&](uint32_t base, size_t srcoff){
        #pragma unroll
        for (int r = 0; r < 8; r++){
            int id = r*256 + tid;
            int plane = id >> 10, rem = id & 1023;
            int row = rem >> 3, f = rem & 7;
            const __nv_bfloat16* src = (plane ? g_El : g_Eh) + srcoff + (size_t)row*ED + f*8;
            cpa16(base + plane*SB_LO + row*144 + f*16, src);
        }
    };

    copy_tile(smb, embase);
    copy_tile(smb + SB_TILE*2, egbase);
    CP_COMMIT();
    copy_tile(smb + 2*SB_TILE*2, egbase + (size_t)128*ED);
    CP_COMMIT();

    const int g = lane >> 2, t = lane & 3;
    const int rowbase = gb*MN + mt*128;
    float rsum_acc[4][2] = {};

    for (int nt = 0; nt < 8; nt++){
        if (nt < 7) { CP_WAIT(1); } else { CP_WAIT(0); }
        __syncthreads();

        const uint32_t enaddr = smb + (1 + (nt & 1))*SB_TILE*2;
        float c4[4][4][4] = {};
        #pragma unroll
        for (int kk = 0; kk < 64; kk += 16)
            mma_step_ldsm<SB_PITCH>(smb, enaddr, SB_LO, SB_LO, kk, wy, wx, lane, c4);
        __syncthreads();

        if (nt + 2 <= 7){
            copy_tile(smb + (1 + ((nt + 2) & 1))*SB_TILE*2, egbase + (size_t)((nt+2)*128)*ED);
            CP_COMMIT();
        }

        #pragma unroll
        for (int i = 0; i < 4; i++){
            #pragma unroll
            for (int h = 0; h < 2; h++){
                const int row = rowbase + wy*64 + i*16 + g + h*8;
                const size_t soff = (size_t)row*MN + nt*128;
                float rsum = 0.f;
                #pragma unroll
                for (int j = 0; j < 4; j++){
                    float v0 = fmaxf(c4[i][j][h*2+0], 0.f);
                    float v1 = fmaxf(c4[i][j][h*2+1], 0.f);
                    rsum += v0 + v1;
                    __half2 p = __floats2half2_rn(v0, v1);
                    *(uint32_t*)&g_S[soff + wx*32 + j*8 + 2*t] = *(uint32_t*)&p;
                }
                rsum_acc[i][h] += rsum;
            }
        }
    }

    #pragma unroll
    for (int i = 0; i < 4; i++){
        #pragma unroll
        for (int h = 0; h < 2; h++){
            float rsum = rsum_acc[i][h];
            rsum += __shfl_xor_sync(0xFFFFFFFFu, rsum, 1);
            rsum += __shfl_xor_sync(0xFFFFFFFFu, rsum, 2);
            if (t == 0){
                const int row = rowbase + wy*64 + i*16 + g + h*8;
                g_degp[row*4 + wx] = rsum;
            }
        }
    }
}

// ============================================================================
// Kernel 2: dinv = rsqrt(1 + sum of 4 partials)
// ============================================================================
__global__ void k_dinv()
{
    const int i = blockIdx.x*256 + threadIdx.x;
    float s = 1.0f;
    #pragma unroll
    for (int j = 0; j < 4; j++) s += g_degp[i*4 + j];
    g_dinv[i] = rsqrtf(s);
}

// ============================================================================
// Kernel 3: Z = dinv ⊙ (In @ W^T); smem-staged transpose; fp16 split planes.
// ============================================================================
#define GW_PITCH 40
#define GW_TILE  (128*GW_PITCH)
#define GW_STAGE (2*GW_TILE)
#define GW_SMEM  (2*GW_STAGE*4)         // 81920 B
#define TP 264

__global__ void __launch_bounds__(256,2) k_gemmw(const float* __restrict__ xin,
                                                 const float* __restrict__ W,
                                                 int use_internal)
{
    extern __shared__ float sm[];
    const uint32_t smb = smem_u32(sm);
    const float* __restrict__ in = use_internal ? g_y : xin;
    const int tid = threadIdx.x, lane = tid & 31, wid = tid >> 5;
    const int wy = wid >> 2, wx = wid & 3;
    const int rbase = blockIdx.x*128;

    auto copy = [&](int c){
        const uint32_t ab = smb + (uint32_t)(c & 1)*GW_STAGE*4;
        const uint32_t bb = ab + GW_TILE*4;
        #pragma unroll
        for (int r = 0; r < 4; r++){
            int id = r*256 + tid;
            int m = id >> 3, f = id & 7;
            cpa16(ab + m*160 + f*16, in + (size_t)(rbase + m)*128 + c*32 + f*4);
            cpa16(bb + m*160 + f*16, W  + (size_t)m*128          + c*32 + f*4);
        }
        CP_COMMIT();
    };

    float c4[4][4][4] = {};
    copy(0);
    for (int c = 0; c < 4; c++){
        if (c < 3){ copy(c + 1); CP_WAIT(1); } else { CP_WAIT(0); }
        __syncthreads();
        const float* As = sm + (c & 1)*GW_STAGE;
        const float* Bs = As + GW_TILE;
        #pragma unroll
        for (int kk = 0; kk < 32; kk += 16)
            mma_step_f32<GW_PITCH, GW_PITCH>(As, Bs, kk, wy, wx, lane, c4);
        __syncthreads();
    }

    const int g = lane >> 2, t = lane & 3;
    const int gb = rbase >> 10;
    const int nbase = rbase & 1023;
    __half* tb = (__half*)sm;

    #pragma unroll
    for (int i = 0; i < 4; i++){
        #pragma unroll
        for (int h = 0; h < 2; h++){
            const int lrow = wy*64 + i*16 + g + h*8;
            const float sc = g_dinv[rbase + lrow];
            float* zr = g_z + (size_t)(rbase + lrow)*128;
            #pragma unroll
            for (int j = 0; j < 4; j++){
                const int col = wx*32 + j*8 + 2*t;
                float v0 = sc*c4[i][j][h*2], v1 = sc*c4[i][j][h*2+1];
                *(float2*)&zr[col] = make_float2(v0, v1);
                __half h0 = __float2half_rn(v0);
                __half h1 = __float2half_rn(v1);
                tb[(col    )*TP + lrow]       = h0;
                tb[(col + 1)*TP + lrow]       = h1;
                tb[(col    )*TP + 128 + lrow] = __float2half_rn(v0 - __half2float(h0));
                tb[(col + 1)*TP + 128 + lrow] = __float2half_rn(v1 - __half2float(h1));
            }
        }
    }
    __syncthreads();

    #pragma unroll
    for (int r = 0; r < 16; r++){
        int id = r*256 + tid;
        int plane = id >> 11, rem = id & 2047;
        int d = rem >> 4, f = rem & 15;
        uint4 v = *(const uint4*)&tb[d*TP + plane*128 + f*8];
        __half* dstp = (plane ? g_ztl : g_zth) + ((size_t)gb*DF + d)*MN + nbase + f*8;
        *(uint4*)dstp = v;
    }
}

// ============================================================================
// Kernel 4: propagation (fp16 2-pass).  out = relu(dinv⊙(S@Z + Z)).
// K=1024: 32 chunks k32, 3-stage, 1 barrier/chunk, staggered, LDSM.
// smem/stage: S 128x[32 fp16 + pad] rows of 80 B = 10240 B;
//             Zt 128x[32hi|32lo fp16 + pad] rows of 144 B = 18432 B.
// grid (8 mt, 32 g), 256 threads, 2 CTAs/SM (3 x 28672 = 86016 B).
// ============================================================================
#define PR_SPITCH 40                    // fp16 elems (80 B rows)
#define PR_ZPITCH 72                    // fp16 elems (144 B rows)
#define PR_SMAT   10240
#define PR_ZMAT   18432
#define PR_STAGE  (PR_SMAT + PR_ZMAT)   // 28672 B
#define PR_NSTG   3
#define PR_SMEM   (PR_NSTG*PR_STAGE)    // 86016 B

__global__ void __launch_bounds__(256,2) k_prop(float* __restrict__ outext, int to_internal)
{
    extern __shared__ __half smhf[];
    const uint32_t smb = smem_u32(smhf);
    const int tid = threadIdx.x, lane = tid & 31, wid = tid >> 5;
    const int wy = wid >> 2, wx = wid & 3;
    const int mt = blockIdx.x, gb = blockIdx.y;
    float* __restrict__ dst = to_internal ? g_y : outext;

    const int mrow0 = gb*MN + mt*128;
    const int phase = (mt & 1)*16;      // stagger co-resident CTAs

    // coverage: S 128x4 ops (512) + Zt 128x8 ops (1024) = 1536 = 6 rounds x 256
    auto copy = [&](int l){
        const int c = (l + phase) & 31;
        const uint32_t sb = smb + (uint32_t)(l % PR_NSTG)*PR_STAGE;
        #pragma unroll
        for (int r = 0; r < 6; r++){
            int id = r*256 + tid;
            if (id < 512){
                int row = id >> 2, f = id & 3;
                const __half* src = g_S + (size_t)(mrow0 + row)*MN + c*32 + f*8;
                cpa16(sb + row*80 + f*16, src);
            } else {
                int id2 = id - 512;
                int d = id2 >> 3, o = id2 & 7;
                int half_ = o >> 2, f = o & 3;
                const __half* src = (half_ ? g_ztl : g_zth)
                    + ((size_t)gb*DF + d)*MN + c*32 + f*8;
                cpa16(sb + PR_SMAT + d*144 + half_*64 + f*16, src);
            }
        }
        CP_COMMIT();
    };

    float c4[4][4][4] = {};
    copy(0); copy(1);
    for (int l = 0; l < 32; l++){
        if (l < 31) { CP_WAIT(1); } else { CP_WAIT(0); }
        __syncthreads();
        const uint32_t A = smb + (uint32_t)(l % PR_NSTG)*PR_STAGE;
        const uint32_t B = A + PR_SMAT;
        #pragma unroll
        for (int kk = 0; kk < 32; kk += 16)
            mma_step_h16<PR_SPITCH, PR_ZPITCH>(A, B, kk, wy, wx, lane, c4);
        if (l + 2 < 32) copy(l + 2);
    }

    const int g = lane >> 2, t = lane & 3;
    #pragma unroll
    for (int i = 0; i < 4; i++){
        #pragma unroll
        for (int h = 0; h < 2; h++){
            const int row = mrow0 + wy*64 + i*16 + g + h*8;
            const float sc = g_dinv[row];
            const float* zr = g_z + (size_t)row*128;
            float* orow = dst + (size_t)row*128;
            #pragma unroll
            for (int j = 0; j < 4; j++){
                const int col = wx*32 + j*8 + 2*t;
                float2 z = *(const float2*)&zr[col];
                float2 o;
                o.x = fmaxf(sc*(c4[i][j][h*2]   + z.x), 0.f);
                o.y = fmaxf(sc*(c4[i][j][h*2+1] + z.y), 0.f);
                *(float2*)&orow[col] = o;
            }
        }
    }
}

// ============================================================================
extern "C" void kernel_launch(void* const* d_in, const int* in_sizes, int n_in,
                              void* d_out, int out_size)
{
    (void)in_sizes; (void)n_in; (void)out_size;
    const float* X  = (const float*)d_in[0];
    const float* E  = (const float*)d_in[1];
    const float* W1 = (const float*)d_in[2];
    const float* W2 = (const float*)d_in[3];
    float* out = (float*)d_out;

    cudaFuncSetAttribute(k_sbuild, cudaFuncAttributeMaxDynamicSharedMemorySize, SB_SMEM);
    cudaFuncSetAttribute(k_gemmw,  cudaFuncAttributeMaxDynamicSharedMemorySize, GW_SMEM);
    cudaFuncSetAttribute(k_prop,   cudaFuncAttributeMaxDynamicSharedMemorySize, PR_SMEM);

    k_esplit<<<2048, 256>>>(E);
    k_sbuild<<<dim3(8, 32), 256, SB_SMEM>>>();
    k_dinv  <<<NROWS/256, 256>>>();
    k_gemmw <<<256, 256, GW_SMEM>>>(X, W1, 0);
    k_prop  <<<dim3(8, 32), 256, PR_SMEM>>>(nullptr, 1);
    k_gemmw <<<256, 256, GW_SMEM>>>(nullptr, W2, 1);
    k_prop  <<<dim3(8, 32), 256, PR_SMEM>>>(out, 0);
}

// round 17
// speedup vs baseline: 2.1193x; 1.4055x over previous
#include <cuda_runtime.h>
#include <cuda_bf16.h>
#include <cuda_fp16.h>
#include <cstdint>

#define BATCH 32
#define MN    1024
#define DF    128
#define ED    64
#define NROWS (BATCH*MN)   // 32768

// ---------------- device scratch ----------------
__device__ __align__(16) __half g_Ef[(size_t)NROWS*ED];       // 4 MB (fp16 E)
__device__ __align__(16) __half g_S [(size_t)BATCH*MN*MN];    // 64 MB (fp16 S)
__device__ float   g_degp[NROWS*4];
__device__ float   g_dinv[NROWS];
__device__ float   g_z  [(size_t)NROWS*DF];
__device__ __align__(16) __half g_zt[(size_t)BATCH*DF*MN];    // Z^T fp16 [g][d][n]
__device__ float   g_y  [(size_t)NROWS*DF];

// ---------------- helpers ----------------
__device__ __forceinline__ uint32_t smem_u32(const void* p){
    uint32_t a;
    asm("{ .reg .u64 t; cvta.to.shared.u64 t, %1; cvt.u32.u64 %0, t; }" : "=r"(a) : "l"(p));
    return a;
}
__device__ __forceinline__ void cpa16(uint32_t d, const void* s){
    asm volatile("cp.async.cg.shared.global [%0], [%1], 16;" :: "r"(d), "l"(s));
}
#define CP_COMMIT() asm volatile("cp.async.commit_group;" ::: "memory")
#define CP_WAIT(n)  asm volatile("cp.async.wait_group %0;" :: "n"(n) : "memory")

__device__ __forceinline__ void ldsm_x4(uint32_t& r0, uint32_t& r1, uint32_t& r2,
                                        uint32_t& r3, uint32_t addr){
    asm volatile("ldmatrix.sync.aligned.m8n8.x4.shared.b16 {%0,%1,%2,%3}, [%4];"
        : "=r"(r0), "=r"(r1), "=r"(r2), "=r"(r3) : "r"(addr));
}

// bf16 split (kept for the fp32-accurate gemmw path)
__device__ __forceinline__ void bsplit2(float v0, float v1, uint32_t& h01, uint32_t& l01){
    asm("cvt.rn.bf16x2.f32 %0, %1, %2;" : "=r"(h01) : "f"(v1), "f"(v0));
    float h0 = __uint_as_float(h01 << 16);
    float h1 = __uint_as_float(h01 & 0xFFFF0000u);
    float l0 = v0 - h0, l1 = v1 - h1;
    asm("cvt.rn.bf16x2.f32 %0, %1, %2;" : "=r"(l01) : "f"(l1), "f"(l0));
}

__device__ __forceinline__ void mma16(float c[4], const uint32_t a[4], const uint32_t b[2]){
    asm volatile(
        "mma.sync.aligned.m16n8k16.row.col.f32.bf16.bf16.f32 "
        "{%0,%1,%2,%3}, {%4,%5,%6,%7}, {%8,%9}, {%0,%1,%2,%3};"
        : "+f"(c[0]), "+f"(c[1]), "+f"(c[2]), "+f"(c[3])
        : "r"(a[0]), "r"(a[1]), "r"(a[2]), "r"(a[3]), "r"(b[0]), "r"(b[1]));
}
__device__ __forceinline__ void mma16h(float c[4], const uint32_t a[4], const uint32_t b[2]){
    asm volatile(
        "mma.sync.aligned.m16n8k16.row.col.f32.f16.f16.f32 "
        "{%0,%1,%2,%3}, {%4,%5,%6,%7}, {%8,%9}, {%0,%1,%2,%3};"
        : "+f"(c[0]), "+f"(c[1]), "+f"(c[2]), "+f"(c[3])
        : "r"(a[0]), "r"(a[1]), "r"(a[2]), "r"(a[3]), "r"(b[0]), "r"(b[1]));
}

// 1-pass fp16 k16 step, single planes.  A [m][k] pitch PA; B [n][k] pitch PB.
// B loaded as paired-n x4: mats {n0 k0, n0 k8, n1 k0, n1 k8}.
template<int PA, int PB>
__device__ __forceinline__ void mma_step_h1(uint32_t Aaddr, uint32_t Baddr,
                                            int kk, int wy, int wx, int lane,
                                            float c4[4][4][4])
{
    uint32_t a4[4][4], b4[2][4];
    const uint32_t aoff = Aaddr +
        (uint32_t)(((wy*64 + (lane & 15))*PA + kk + ((lane >> 4)*8))*2);
    #pragma unroll
    for (int i = 0; i < 4; i++)
        ldsm_x4(a4[i][0], a4[i][1], a4[i][2], a4[i][3], aoff + i*(16*PA*2));

    #pragma unroll
    for (int jj = 0; jj < 2; jj++){
        const uint32_t boff = Baddr +
            (uint32_t)(((wx*32 + jj*16 + (lane & 7))*PB + kk + (((lane >> 3) & 1)*8))*2)
            + (uint32_t)(lane >> 4)*(8*PB*2);
        ldsm_x4(b4[jj][0], b4[jj][1], b4[jj][2], b4[jj][3], boff);
    }

    #pragma unroll
    for (int jj = 0; jj < 2; jj++)
        #pragma unroll
        for (int h = 0; h < 2; h++)
            #pragma unroll
            for (int i = 0; i < 4; i++)
                mma16h(c4[i][jj*2 + h], a4[i], &b4[jj][h*2]);
}

// bf16 split k16 step from fp32 smem tiles (gemmw path, full accuracy).
template<int PA, int PB>
__device__ __forceinline__ void mma_step_f32(const float* __restrict__ As,
                                             const float* __restrict__ Bs,
                                             int kk, int wy, int wx, int lane,
                                             float c4[4][4][4])
{
    const int g = lane >> 2, t = lane & 3;
    uint32_t ah[4][4], al[4][4], bh[4][2], bl[4][2];
    #pragma unroll
    for (int i = 0; i < 4; i++){
        const float* ap = As + (wy*64 + i*16 + g)*PA + kk + 2*t;
        float2 v;
        v = *(const float2*)(ap);            bsplit2(v.x, v.y, ah[i][0], al[i][0]);
        v = *(const float2*)(ap + 8*PA);     bsplit2(v.x, v.y, ah[i][1], al[i][1]);
        v = *(const float2*)(ap + 8);        bsplit2(v.x, v.y, ah[i][2], al[i][2]);
        v = *(const float2*)(ap + 8*PA + 8); bsplit2(v.x, v.y, ah[i][3], al[i][3]);
    }
    #pragma unroll
    for (int j = 0; j < 4; j++){
        const float* bp = Bs + (wx*32 + j*8 + g)*PB + kk + 2*t;
        float2 v;
        v = *(const float2*)(bp);     bsplit2(v.x, v.y, bh[j][0], bl[j][0]);
        v = *(const float2*)(bp + 8); bsplit2(v.x, v.y, bh[j][1], bl[j][1]);
    }
    #pragma unroll
    for (int j = 0; j < 4; j++)
        #pragma unroll
        for (int i = 0; i < 4; i++) mma16(c4[i][j], ah[i], bh[j]);
    #pragma unroll
    for (int j = 0; j < 4; j++)
        #pragma unroll
        for (int i = 0; i < 4; i++) mma16(c4[i][j], al[i], bh[j]);
    #pragma unroll
    for (int j = 0; j < 4; j++)
        #pragma unroll
        for (int i = 0; i < 4; i++) mma16(c4[i][j], ah[i], bl[j]);
}

// ============================================================================
// Kernel 0: convert E to fp16 plane.
// ============================================================================
__global__ void k_esplit(const float* __restrict__ E)
{
    const int id = blockIdx.x*256 + threadIdx.x;      // 524288 float4
    float4 v = *(const float4*)(E + (size_t)id*4);
    __half2 p0 = __floats2half2_rn(v.x, v.y);
    __half2 p1 = __floats2half2_rn(v.z, v.w);
    *(uint2*)&g_Ef[(size_t)id*4] = make_uint2(*(uint32_t*)&p0, *(uint32_t*)&p1);
}

// ============================================================================
// Kernel 1: S-build (1-pass fp16).  S tile = relu(Em En^T); fp16 store;
// fp32 row-sum partials.  grid (8 mt, 32 g), 256 threads, 2 CTAs/SM.
// ============================================================================
#define SB_PITCH 72                          // fp16; 144 B rows
#define SB_TILE  (128*SB_PITCH*2)            // 18432 B per tile
#define SB_SMEM  (3*SB_TILE)                 // Em + 2 En stages = 55296 B

__global__ void __launch_bounds__(256,2) k_sbuild()
{
    extern __shared__ __half smhf[];
    const uint32_t smb = smem_u32(smhf);
    const int tid = threadIdx.x, lane = tid & 31, wid = tid >> 5;
    const int wy = wid >> 2, wx = wid & 3;
    const int mt = blockIdx.x, gb = blockIdx.y;

    const size_t embase = (size_t)(gb*MN + mt*128)*ED;
    const size_t egbase = (size_t)gb*MN*ED;

    // coverage: 128 rows x 8 ops(16B) = 1024 = 4 rounds x 256 thr
    auto copy_tile = [&](uint32_t base, size_t srcoff){
        #pragma unroll
        for (int r = 0; r < 4; r++){
            int id = r*256 + tid;
            int row = id >> 3, f = id & 7;
            cpa16(base + row*144 + f*16, g_Ef + srcoff + (size_t)row*ED + f*8);
        }
    };

    copy_tile(smb, embase);
    copy_tile(smb + SB_TILE, egbase);
    CP_COMMIT();
    copy_tile(smb + 2*SB_TILE, egbase + (size_t)128*ED);
    CP_COMMIT();

    const int g = lane >> 2, t = lane & 3;
    const int rowbase = gb*MN + mt*128;
    float rsum_acc[4][2] = {};

    for (int nt = 0; nt < 8; nt++){
        if (nt < 7) { CP_WAIT(1); } else { CP_WAIT(0); }
        __syncthreads();

        const uint32_t enaddr = smb + (1 + (nt & 1))*SB_TILE;
        float c4[4][4][4] = {};
        #pragma unroll
        for (int kk = 0; kk < 64; kk += 16)
            mma_step_h1<SB_PITCH, SB_PITCH>(smb, enaddr, kk, wy, wx, lane, c4);
        __syncthreads();

        if (nt + 2 <= 7){
            copy_tile(smb + (1 + ((nt + 2) & 1))*SB_TILE, egbase + (size_t)((nt+2)*128)*ED);
            CP_COMMIT();
        }

        #pragma unroll
        for (int i = 0; i < 4; i++){
            #pragma unroll
            for (int h = 0; h < 2; h++){
                const int row = rowbase + wy*64 + i*16 + g + h*8;
                const size_t soff = (size_t)row*MN + nt*128;
                float rsum = 0.f;
                #pragma unroll
                for (int j = 0; j < 4; j++){
                    float v0 = fmaxf(c4[i][j][h*2+0], 0.f);
                    float v1 = fmaxf(c4[i][j][h*2+1], 0.f);
                    rsum += v0 + v1;
                    __half2 p = __floats2half2_rn(v0, v1);
                    *(uint32_t*)&g_S[soff + wx*32 + j*8 + 2*t] = *(uint32_t*)&p;
                }
                rsum_acc[i][h] += rsum;
            }
        }
    }

    #pragma unroll
    for (int i = 0; i < 4; i++){
        #pragma unroll
        for (int h = 0; h < 2; h++){
            float rsum = rsum_acc[i][h];
            rsum += __shfl_xor_sync(0xFFFFFFFFu, rsum, 1);
            rsum += __shfl_xor_sync(0xFFFFFFFFu, rsum, 2);
            if (t == 0){
                const int row = rowbase + wy*64 + i*16 + g + h*8;
                g_degp[row*4 + wx] = rsum;
            }
        }
    }
}

// ============================================================================
// Kernel 2: dinv = rsqrt(1 + sum of 4 partials)
// ============================================================================
__global__ void k_dinv()
{
    const int i = blockIdx.x*256 + threadIdx.x;
    float s = 1.0f;
    #pragma unroll
    for (int j = 0; j < 4; j++) s += g_degp[i*4 + j];
    g_dinv[i] = rsqrtf(s);
}

// ============================================================================
// Kernel 3: Z = dinv ⊙ (In @ W^T); smem-staged transpose; fp16 Z^T plane.
// ============================================================================
#define GW_PITCH 40
#define GW_TILE  (128*GW_PITCH)
#define GW_STAGE (2*GW_TILE)
#define GW_SMEM  (2*GW_STAGE*4)         // 81920 B
#define TP 136                          // transpose pitch (fp16): 128 + 8 pad

__global__ void __launch_bounds__(256,2) k_gemmw(const float* __restrict__ xin,
                                                 const float* __restrict__ W,
                                                 int use_internal)
{
    extern __shared__ float sm[];
    const uint32_t smb = smem_u32(sm);
    const float* __restrict__ in = use_internal ? g_y : xin;
    const int tid = threadIdx.x, lane = tid & 31, wid = tid >> 5;
    const int wy = wid >> 2, wx = wid & 3;
    const int rbase = blockIdx.x*128;

    auto copy = [&](int c){
        const uint32_t ab = smb + (uint32_t)(c & 1)*GW_STAGE*4;
        const uint32_t bb = ab + GW_TILE*4;
        #pragma unroll
        for (int r = 0; r < 4; r++){
            int id = r*256 + tid;
            int m = id >> 3, f = id & 7;
            cpa16(ab + m*160 + f*16, in + (size_t)(rbase + m)*128 + c*32 + f*4);
            cpa16(bb + m*160 + f*16, W  + (size_t)m*128          + c*32 + f*4);
        }
        CP_COMMIT();
    };

    float c4[4][4][4] = {};
    copy(0);
    for (int c = 0; c < 4; c++){
        if (c < 3){ copy(c + 1); CP_WAIT(1); } else { CP_WAIT(0); }
        __syncthreads();
        const float* As = sm + (c & 1)*GW_STAGE;
        const float* Bs = As + GW_TILE;
        #pragma unroll
        for (int kk = 0; kk < 32; kk += 16)
            mma_step_f32<GW_PITCH, GW_PITCH>(As, Bs, kk, wy, wx, lane, c4);
        __syncthreads();
    }

    const int g = lane >> 2, t = lane & 3;
    const int gb = rbase >> 10;
    const int nbase = rbase & 1023;
    __half* tb = (__half*)sm;           // 128 cols x TP rows

    #pragma unroll
    for (int i = 0; i < 4; i++){
        #pragma unroll
        for (int h = 0; h < 2; h++){
            const int lrow = wy*64 + i*16 + g + h*8;
            const float sc = g_dinv[rbase + lrow];
            float* zr = g_z + (size_t)(rbase + lrow)*128;
            #pragma unroll
            for (int j = 0; j < 4; j++){
                const int col = wx*32 + j*8 + 2*t;
                float v0 = sc*c4[i][j][h*2], v1 = sc*c4[i][j][h*2+1];
                *(float2*)&zr[col] = make_float2(v0, v1);
                tb[(col    )*TP + lrow] = __float2half_rn(v0);
                tb[(col + 1)*TP + lrow] = __float2half_rn(v1);
            }
        }
    }
    __syncthreads();

    // coverage: 128 d x 16 ops = 2048 = 8 rounds x 256 thr
    #pragma unroll
    for (int r = 0; r < 8; r++){
        int id = r*256 + tid;
        int d = id >> 4, f = id & 15;
        uint4 v = *(const uint4*)&tb[d*TP + f*8];
        *(uint4*)(g_zt + ((size_t)gb*DF + d)*MN + nbase + f*8) = v;
    }
}

// ============================================================================
// Kernel 4: propagation (1-pass fp16).  out = relu(dinv⊙(S@Z + Z)).
// K=1024: 32 chunks k32, 3-stage, 1 barrier/chunk, staggered, LDSM.
// Stage: S 128x[32+8 pad] fp16 = 10240 B; Zt same = 10240 B.
// grid (8 mt, 32 g), 256 threads, 2 CTAs/SM (3 x 20480 = 61440 B).
// ============================================================================
#define PR_PITCH 40
#define PR_MAT   10240
#define PR_STAGE (2*PR_MAT)             // 20480 B
#define PR_NSTG  3
#define PR_SMEM  (PR_NSTG*PR_STAGE)     // 61440 B

__global__ void __launch_bounds__(256,2) k_prop(float* __restrict__ outext, int to_internal)
{
    extern __shared__ __half smhf[];
    const uint32_t smb = smem_u32(smhf);
    const int tid = threadIdx.x, lane = tid & 31, wid = tid >> 5;
    const int wy = wid >> 2, wx = wid & 3;
    const int mt = blockIdx.x, gb = blockIdx.y;
    float* __restrict__ dst = to_internal ? g_y : outext;

    const int mrow0 = gb*MN + mt*128;
    const int phase = (mt & 1)*16;      // stagger co-resident CTAs

    // coverage: S 512 ops + Zt 512 ops = 1024 = 4 rounds x 256 thr
    auto copy = [&](int l){
        const int c = (l + phase) & 31;
        const uint32_t sb = smb + (uint32_t)(l % PR_NSTG)*PR_STAGE;
        #pragma unroll
        for (int r = 0; r < 4; r++){
            int id = r*256 + tid;
            if (id < 512){
                int row = id >> 2, f = id & 3;
                cpa16(sb + row*80 + f*16,
                      g_S + (size_t)(mrow0 + row)*MN + c*32 + f*8);
            } else {
                int id2 = id - 512;
                int d = id2 >> 2, f = id2 & 3;
                cpa16(sb + PR_MAT + d*80 + f*16,
                      g_zt + ((size_t)gb*DF + d)*MN + c*32 + f*8);
            }
        }
        CP_COMMIT();
    };

    float c4[4][4][4] = {};
    copy(0); copy(1);
    for (int l = 0; l < 32; l++){
        if (l < 31) { CP_WAIT(1); } else { CP_WAIT(0); }
        __syncthreads();
        const uint32_t A = smb + (uint32_t)(l % PR_NSTG)*PR_STAGE;
        const uint32_t B = A + PR_MAT;
        #pragma unroll
        for (int kk = 0; kk < 32; kk += 16)
            mma_step_h1<PR_PITCH, PR_PITCH>(A, B, kk, wy, wx, lane, c4);
        if (l + 2 < 32) copy(l + 2);
    }

    const int g = lane >> 2, t = lane & 3;
    #pragma unroll
    for (int i = 0; i < 4; i++){
        #pragma unroll
        for (int h = 0; h < 2; h++){
            const int row = mrow0 + wy*64 + i*16 + g + h*8;
            const float sc = g_dinv[row];
            const float* zr = g_z + (size_t)row*128;
            float* orow = dst + (size_t)row*128;
            #pragma unroll
            for (int j = 0; j < 4; j++){
                const int col = wx*32 + j*8 + 2*t;
                float2 z = *(const float2*)&zr[col];
                float2 o;
                o.x = fmaxf(sc*(c4[i][j][h*2]   + z.x), 0.f);
                o.y = fmaxf(sc*(c4[i][j][h*2+1] + z.y), 0.f);
                *(float2*)&orow[col] = o;
            }
        }
    }
}

// ============================================================================
extern "C" void kernel_launch(void* const* d_in, const int* in_sizes, int n_in,
                              void* d_out, int out_size)
{
    (void)in_sizes; (void)n_in; (void)out_size;
    const float* X  = (const float*)d_in[0];
    const float* E  = (const float*)d_in[1];
    const float* W1 = (const float*)d_in[2];
    const float* W2 = (const float*)d_in[3];
    float* out = (float*)d_out;

    cudaFuncSetAttribute(k_sbuild, cudaFuncAttributeMaxDynamicSharedMemorySize, SB_SMEM);
    cudaFuncSetAttribute(k_gemmw,  cudaFuncAttributeMaxDynamicSharedMemorySize, GW_SMEM);
    cudaFuncSetAttribute(k_prop,   cudaFuncAttributeMaxDynamicSharedMemorySize, PR_SMEM);

    k_esplit<<<2048, 256>>>(E);
    k_sbuild<<<dim3(8, 32), 256, SB_SMEM>>>();
    k_dinv  <<<NROWS/256, 256>>>();
    k_gemmw <<<256, 256, GW_SMEM>>>(X, W1, 0);
    k_prop  <<<dim3(8, 32), 256, PR_SMEM>>>(nullptr, 1);
    k_gemmw <<<256, 256, GW_SMEM>>>(nullptr, W2, 1);
    k_prop  <<<dim3(8, 32), 256, PR_SMEM>>>(out, 0);
}